// round 9
// baseline (speedup 1.0000x reference)
#include <cuda_runtime.h>
#include <cuda_bf16.h>
#include <math.h>
#include <stdint.h>

#define NN 100000
#define EE 1600000
#define FF 128
#define HH 256
#define GG 512
#define CC 10
#define LREST 3
#define BN_EPS 1e-5f

// ---------------- scratch (static device arrays; no allocation) --------------
__device__ float g_agg [(size_t)NN * HH];
__device__ float g_bufA[(size_t)NN * HH];
__device__ float g_bufB[(size_t)NN * HH];
__device__ float g_pooled[GG * HH];
__device__ float g_counts[GG];
__device__ __nv_bfloat16 g_wh[8 * 65536];   // weight hi parts, [K][N] natural layout
__device__ __nv_bfloat16 g_wl[8 * 65536];   // weight lo parts
// CSR build
__device__ int g_cnt[NN];
__device__ int g_off[NN];
__device__ int g_cursor[NN];
__device__ int g_ssrc[EE];
__device__ int g_bsum[128];
__device__ int g_boff[128];

// ---------------- helpers ----------------------------------------------------
__device__ __forceinline__ uint32_t smem_u32(const void* p) {
    uint32_t r;
    asm("{ .reg .u64 t; cvta.to.shared.u64 t, %1; cvt.u32.u64 %0, t; }" : "=r"(r) : "l"(p));
    return r;
}
__device__ __forceinline__ void bsplit2(float e, float o, uint32_t& hi, uint32_t& lo) {
    __nv_bfloat16 he = __float2bfloat16_rn(e);
    __nv_bfloat16 ho = __float2bfloat16_rn(o);
    float re = e - __bfloat162float(he);
    float ro = o - __bfloat162float(ho);
    __nv_bfloat16 le  = __float2bfloat16_rn(re);
    __nv_bfloat16 lo_ = __float2bfloat16_rn(ro);
    hi = ((uint32_t)__bfloat16_as_ushort(ho) << 16) | (uint32_t)__bfloat16_as_ushort(he);
    lo = ((uint32_t)__bfloat16_as_ushort(lo_) << 16) | (uint32_t)__bfloat16_as_ushort(le);
}
__device__ __forceinline__ void mma16816(float* d, const uint32_t* a, uint32_t b0, uint32_t b1) {
    asm volatile("mma.sync.aligned.m16n8k16.row.col.f32.bf16.bf16.f32 "
                 "{%0,%1,%2,%3}, {%4,%5,%6,%7}, {%8,%9}, {%0,%1,%2,%3};"
                 : "+f"(d[0]), "+f"(d[1]), "+f"(d[2]), "+f"(d[3])
                 : "r"(a[0]), "r"(a[1]), "r"(a[2]), "r"(a[3]), "r"(b0), "r"(b1));
}
__device__ __forceinline__ void ldsm4(uint32_t* r, uint32_t addr) {
    asm volatile("ldmatrix.sync.aligned.m8n8.x4.shared.b16 {%0,%1,%2,%3}, [%4];"
                 : "=r"(r[0]), "=r"(r[1]), "=r"(r[2]), "=r"(r[3]) : "r"(addr));
}
__device__ __forceinline__ void ldsm4t(uint32_t* r, uint32_t addr) {
    asm volatile("ldmatrix.sync.aligned.m8n8.x4.trans.shared.b16 {%0,%1,%2,%3}, [%4];"
                 : "=r"(r[0]), "=r"(r[1]), "=r"(r[2]), "=r"(r[3]) : "r"(addr));
}
__device__ __forceinline__ void cpasync16(uint32_t s, const void* g) {
    asm volatile("cp.async.ca.shared.global [%0], [%1], 16;"
                 :: "r"(s), "l"(g) : "memory");
}

// ---------------- CSR build ---------------------------------------------------
__global__ void zero_cnt_kernel() {
    int i = blockIdx.x * blockDim.x + threadIdx.x;
    if (i < NN) g_cnt[i] = 0;
}
__global__ void hist_kernel(const int* __restrict__ dst) {
    int e = blockIdx.x * blockDim.x + threadIdx.x;
    if (e < EE) atomicAdd(&g_cnt[dst[e]], 1);
}
__global__ __launch_bounds__(1024)
void scan1_kernel() {
    __shared__ int sh[1024];
    int i = blockIdx.x * 1024 + threadIdx.x;
    int v = (i < NN) ? g_cnt[i] : 0;
    sh[threadIdx.x] = v;
    __syncthreads();
    for (int o = 1; o < 1024; o <<= 1) {
        int t = (threadIdx.x >= o) ? sh[threadIdx.x - o] : 0;
        __syncthreads();
        sh[threadIdx.x] += t;
        __syncthreads();
    }
    if (i < NN) g_off[i] = sh[threadIdx.x] - v;
    if (threadIdx.x == 1023) g_bsum[blockIdx.x] = sh[1023];
}
__global__ void scan2_kernel(int nb) {
    if (threadIdx.x == 0) {
        int run = 0;
        for (int b = 0; b < nb; b++) { g_boff[b] = run; run += g_bsum[b]; }
    }
}
__global__ __launch_bounds__(1024)
void scan3_kernel() {
    int i = blockIdx.x * 1024 + threadIdx.x;
    if (i < NN) {
        int o = g_off[i] + g_boff[blockIdx.x];
        g_off[i] = o;
        g_cursor[i] = o;
    }
}
__global__ void place_kernel(const int* __restrict__ src, const int* __restrict__ dst) {
    int e = blockIdx.x * blockDim.x + threadIdx.x;
    if (e < EE) {
        int p = atomicAdd(&g_cursor[dst[e]], 1);
        g_ssrc[p] = src[e];
    }
}

// ---------------- CSR aggregation: agg[d] = x[d] + sum_{s in N(d)} x[s] ------
template<int W>
__global__ __launch_bounds__(256)
void agg_kernel(const float* __restrict__ x, float* __restrict__ agg) {
    int gtid = blockIdx.x * blockDim.x + threadIdx.x;
    int d = gtid >> 5;
    int lane = gtid & 31;
    if (d >= NN) return;
    constexpr int V = W / 128;
    const float4* xv = (const float4*)x;
    float4 acc[V];
#pragma unroll
    for (int q = 0; q < V; q++) acc[q] = xv[(size_t)d * (W / 4) + lane + 32 * q];

    int beg = g_off[d];
    int cnt = g_cnt[d];
    int j = 0;
    for (; j + 4 <= cnt; j += 4) {
        int s0 = g_ssrc[beg + j];
        int s1 = g_ssrc[beg + j + 1];
        int s2 = g_ssrc[beg + j + 2];
        int s3 = g_ssrc[beg + j + 3];
        float4 v0[V], v1[V], v2[V], v3[V];
#pragma unroll
        for (int q = 0; q < V; q++) v0[q] = xv[(size_t)s0 * (W / 4) + lane + 32 * q];
#pragma unroll
        for (int q = 0; q < V; q++) v1[q] = xv[(size_t)s1 * (W / 4) + lane + 32 * q];
#pragma unroll
        for (int q = 0; q < V; q++) v2[q] = xv[(size_t)s2 * (W / 4) + lane + 32 * q];
#pragma unroll
        for (int q = 0; q < V; q++) v3[q] = xv[(size_t)s3 * (W / 4) + lane + 32 * q];
#pragma unroll
        for (int q = 0; q < V; q++) {
            acc[q].x += (v0[q].x + v1[q].x) + (v2[q].x + v3[q].x);
            acc[q].y += (v0[q].y + v1[q].y) + (v2[q].y + v3[q].y);
            acc[q].z += (v0[q].z + v1[q].z) + (v2[q].z + v3[q].z);
            acc[q].w += (v0[q].w + v1[q].w) + (v2[q].w + v3[q].w);
        }
    }
    for (; j + 2 <= cnt; j += 2) {
        int s0 = g_ssrc[beg + j];
        int s1 = g_ssrc[beg + j + 1];
        float4 v0[V], v1[V];
#pragma unroll
        for (int q = 0; q < V; q++) v0[q] = xv[(size_t)s0 * (W / 4) + lane + 32 * q];
#pragma unroll
        for (int q = 0; q < V; q++) v1[q] = xv[(size_t)s1 * (W / 4) + lane + 32 * q];
#pragma unroll
        for (int q = 0; q < V; q++) {
            acc[q].x += v0[q].x + v1[q].x;
            acc[q].y += v0[q].y + v1[q].y;
            acc[q].z += v0[q].z + v1[q].z;
            acc[q].w += v0[q].w + v1[q].w;
        }
    }
    if (j < cnt) {
        int s0 = g_ssrc[beg + j];
#pragma unroll
        for (int q = 0; q < V; q++) {
            float4 v = xv[(size_t)s0 * (W / 4) + lane + 32 * q];
            acc[q].x += v.x; acc[q].y += v.y; acc[q].z += v.z; acc[q].w += v.w;
        }
    }
    float4* av = (float4*)agg;
#pragma unroll
    for (int q = 0; q < V; q++) av[(size_t)d * (W / 4) + lane + 32 * q] = acc[q];
}

// ---------------- SMEM geometry (GEMM) ---------------------------------------
static constexpr int AST  = 40;            // A row stride (halves): 32 + 8 pad
static constexpr int BST  = 264;           // B row stride (halves): 256 + 8 pad
static constexpr int A_SZ = 128 * AST;     // 5120 halves / buffer
static constexpr int B_SZ = 32 * BST;      // 8448 halves / buffer
static constexpr int SMEM_BYTES2 = (4 * A_SZ + 4 * B_SZ) * 2;  // 108544 B

// ---------------- bf16x3 mma GEMM: BM=128, BN=256 (full), warp tile m64n64 ----
// 8 warps: wm in {0,1} (m64), wn in {0..3} (n64). A reg-staged, B cp.async.
template<int KDIM, int EPI>
__global__ __launch_bounds__(256, 1)
void mma_gemm(const float* __restrict__ A,
              const __nv_bfloat16* __restrict__ Wh,
              const __nv_bfloat16* __restrict__ Wl,
              float* __restrict__ C, int M,
              const float* __restrict__ bias,
              const float* __restrict__ gp, const float* __restrict__ bep,
              const float* __restrict__ rmp, const float* __restrict__ rvp) {
    extern __shared__ __nv_bfloat16 sm[];
    __nv_bfloat16* sAh = sm;
    __nv_bfloat16* sAl = sAh + 2 * A_SZ;
    const uint32_t sAh_u = smem_u32(sAh);
    const uint32_t sAl_u = sAh_u + 2 * A_SZ * 2;
    const uint32_t sBh_u = sAl_u + 2 * A_SZ * 2;
    const uint32_t sBl_u = sBh_u + 2 * B_SZ * 2;

    const int tid  = threadIdx.x;
    const int lane = tid & 31;
    const int wid  = tid >> 5;
    const int wm   = wid >> 2;     // 0..1
    const int wn   = wid & 3;      // 0..3
    const int rowBase = blockIdx.x * 128;
    constexpr int NIT = KDIM / 32;

    float acc[4][8][4];
#pragma unroll
    for (int mi = 0; mi < 4; mi++)
#pragma unroll
        for (int ni = 0; ni < 8; ni++)
#pragma unroll
            for (int q = 0; q < 4; q++) acc[mi][ni][q] = 0.f;

    float4 ar[4];

    auto loadA = [&](int it) {                 // global -> regs
        int k0 = it * 32;
#pragma unroll
        for (int j = 0; j < 4; j++) {
            int i = tid + j * 256;
            int row = i >> 3, c4 = (i & 7) * 4;
            int gm = rowBase + row;
            ar[j] = (gm < M) ? *(const float4*)(A + (size_t)gm * KDIM + k0 + c4)
                             : make_float4(0.f, 0.f, 0.f, 0.f);
        }
    };
    auto storeA = [&](int buf) {               // regs -> smem hi/lo split
#pragma unroll
        for (int j = 0; j < 4; j++) {
            int i = tid + j * 256;
            int row = i >> 3, c4 = (i & 7) * 4;
            uint32_t h0, l0, h1, l1;
            bsplit2(ar[j].x, ar[j].y, h0, l0);
            bsplit2(ar[j].z, ar[j].w, h1, l1);
            uint32_t off = buf * A_SZ + row * AST + c4;
            *(uint2*)(sAh + off) = make_uint2(h0, h1);
            *(uint2*)(sAl + off) = make_uint2(l0, l1);
        }
    };
    auto cpB = [&](int it, int buf) {          // weights: async copy (32x256 hi+lo)
        int k0 = it * 32;
#pragma unroll
        for (int t = 0; t < 4; t++) {
            int c = tid + t * 256;             // 0..1023
            int kr = c >> 5, ci = c & 31;
            size_t goff = (size_t)(k0 + kr) * HH + ci * 8;
            uint32_t soff = (uint32_t)(buf * B_SZ + kr * BST + ci * 8) * 2;
            cpasync16(sBh_u + soff, Wh + goff);
            cpasync16(sBl_u + soff, Wl + goff);
        }
        asm volatile("cp.async.commit_group;" ::: "memory");
    };
    auto compute = [&](int buf) {
        uint32_t aB  = sAh_u + buf * A_SZ * 2;
        uint32_t alB = sAl_u + buf * A_SZ * 2;
        uint32_t bB  = sBh_u + buf * B_SZ * 2;
        uint32_t blB = sBl_u + buf * B_SZ * 2;
#pragma unroll
        for (int kk = 0; kk < 2; kk++) {
            uint32_t ahf[4][4], alf[4][4];
#pragma unroll
            for (int mi = 0; mi < 4; mi++) {
                int row = wm * 64 + mi * 16 + (lane & 15);
                int col = kk * 16 + (lane >> 4) * 8;
                uint32_t o = (uint32_t)(row * AST + col) * 2;
                ldsm4(ahf[mi], aB + o);
                ldsm4(alf[mi], alB + o);
            }
#pragma unroll
            for (int p = 0; p < 4; p++) {
                int kr = kk * 16 + (lane & 15);
                int nc = wn * 64 + p * 16 + (lane >> 4) * 8;
                uint32_t o = (uint32_t)(kr * BST + nc) * 2;
                uint32_t bh[4], bl[4];
                ldsm4t(bh, bB + o);
                ldsm4t(bl, blB + o);
#pragma unroll
                for (int mi = 0; mi < 4; mi++) {
#pragma unroll
                    for (int h = 0; h < 2; h++) {
                        float* d = acc[mi][p * 2 + h];
                        mma16816(d, ahf[mi], bh[2 * h], bh[2 * h + 1]);
                        mma16816(d, ahf[mi], bl[2 * h], bl[2 * h + 1]);
                        mma16816(d, alf[mi], bh[2 * h], bh[2 * h + 1]);
                    }
                }
            }
        }
    };

    // prologue
    cpB(0, 0);
    loadA(0);
    storeA(0);
    asm volatile("cp.async.wait_group 0;" ::: "memory");
    __syncthreads();

    int buf = 0;
    for (int it = 0; it < NIT; ++it) {
        if (it + 1 < NIT) {
            cpB(it + 1, buf ^ 1);
            loadA(it + 1);
        }
        compute(buf);
        if (it + 1 < NIT) {
            storeA(buf ^ 1);
            asm volatile("cp.async.wait_group 0;" ::: "memory");
            __syncthreads();
            buf ^= 1;
        }
    }

    // ---- epilogue ----
    const int g = lane >> 2, t = lane & 3;
#pragma unroll
    for (int ni = 0; ni < 8; ni++) {
        int col = wn * 64 + ni * 8 + t * 2;
        float b0 = __ldg(bias + col), b1 = __ldg(bias + col + 1);
        float sc0 = 1.f, sh0 = 0.f, sc1 = 1.f, sh1 = 0.f;
        if (EPI == 1) {
            float s0 = __ldg(gp + col)     * rsqrtf(__ldg(rvp + col)     + BN_EPS);
            float s1 = __ldg(gp + col + 1) * rsqrtf(__ldg(rvp + col + 1) + BN_EPS);
            sc0 = s0; sh0 = __ldg(bep + col)     - __ldg(rmp + col)     * s0;
            sc1 = s1; sh1 = __ldg(bep + col + 1) - __ldg(rmp + col + 1) * s1;
        }
#pragma unroll
        for (int mi = 0; mi < 4; mi++) {
            int r0 = rowBase + wm * 64 + mi * 16 + g;
#pragma unroll
            for (int half = 0; half < 2; half++) {
                int r = r0 + half * 8;
                if (r < M) {
                    float v0 = fmaxf(acc[mi][ni][half * 2]     + b0, 0.f);
                    float v1 = fmaxf(acc[mi][ni][half * 2 + 1] + b1, 0.f);
                    if (EPI == 1) { v0 = v0 * sc0 + sh0; v1 = v1 * sc1 + sh1; }
                    *(float2*)(C + (size_t)r * HH + col) = make_float2(v0, v1);
                }
            }
        }
    }
}

// ---------------- weight hi/lo pre-split -------------------------------------
__global__ void wconv_kernel(const float* __restrict__ W, __nv_bfloat16* __restrict__ Wh,
                             __nv_bfloat16* __restrict__ Wl, int n) {
    int i = blockIdx.x * blockDim.x + threadIdx.x;
    if (i < n) {
        float f = W[i];
        __nv_bfloat16 h = __float2bfloat16_rn(f);
        Wh[i] = h;
        Wl[i] = __float2bfloat16_rn(f - __bfloat162float(h));
    }
}

// ---------------- pooling ----------------------------------------------------
__global__ void zero_pool_kernel() {
    int i = blockIdx.x * blockDim.x + threadIdx.x;
    if (i < GG * HH) g_pooled[i] = 0.f;
    if (i < GG) g_counts[i] = 0.f;
}
__global__ void pool_kernel(const float* __restrict__ h, const int* __restrict__ batch) {
    int gtid = blockIdx.x * blockDim.x + threadIdx.x;
    int nd = gtid >> 5;
    int lane = gtid & 31;
    if (nd >= NN) return;
    int b = batch[nd];
    const float4* hr = (const float4*)(h + (size_t)nd * HH);
    float4* pr = (float4*)(g_pooled + b * HH);
#pragma unroll
    for (int i = 0; i < 2; ++i) {
        float4 v = hr[lane + 32 * i];
        asm volatile("red.global.add.v4.f32 [%0], {%1,%2,%3,%4};"
                     :: "l"(pr + lane + 32 * i),
                        "f"(v.x), "f"(v.y), "f"(v.z), "f"(v.w)
                     : "memory");
    }
    if (lane == 0) atomicAdd(&g_counts[b], 1.f);
}

// ---------------- head -------------------------------------------------------
__global__ __launch_bounds__(256)
void head_kernel(const float* __restrict__ Wf, const float* __restrict__ bf,
                 const float* __restrict__ Wo, const float* __restrict__ bo,
                 float* __restrict__ out) {
    __shared__ float ps[HH];
    __shared__ float hs[HH];
    __shared__ float ls[CC];
    int gph = blockIdx.x;
    int j = threadIdx.x;

    float cnt = fmaxf(g_counts[gph], 1.f);
    ps[j] = g_pooled[gph * HH + j] / cnt;
    __syncthreads();

    float acc = bf[j];
#pragma unroll 8
    for (int k = 0; k < HH; k++) acc = fmaf(ps[k], Wf[k * HH + j], acc);
    hs[j] = fmaxf(acc, 0.f);
    __syncthreads();

    if (j < CC) {
        float a = bo[j];
#pragma unroll 8
        for (int k = 0; k < HH; k++) a = fmaf(hs[k], Wo[k * CC + j], a);
        ls[j] = a;
    }
    __syncthreads();

    if (j == 0) {
        float m = -1e30f;
#pragma unroll
        for (int c = 0; c < CC; c++) m = fmaxf(m, ls[c]);
        float s = 0.f;
#pragma unroll
        for (int c = 0; c < CC; c++) s += expf(ls[c] - m);
        float lse = m + logf(s);
#pragma unroll
        for (int c = 0; c < CC; c++) out[gph * CC + c] = ls[c] - lse;
    }
}

// ---------------------------------------------------------------------------
extern "C" void kernel_launch(void* const* d_in, const int* in_sizes, int n_in,
                              void* d_out, int out_size) {
    const float* x    = (const float*)d_in[0];
    const int*   ei   = (const int*)  d_in[1];
    const int*   batch= (const int*)  d_in[2];
    const float* W1a  = (const float*)d_in[3];
    const float* b1a  = (const float*)d_in[4];
    const float* W2a  = (const float*)d_in[5];
    const float* b2a  = (const float*)d_in[6];
    const float* g_a  = (const float*)d_in[7];
    const float* be_a = (const float*)d_in[8];
    const float* rm_a = (const float*)d_in[9];
    const float* rv_a = (const float*)d_in[10];
    const float* Ws1  = (const float*)d_in[11];
    const float* bs1  = (const float*)d_in[12];
    const float* Ws2  = (const float*)d_in[13];
    const float* bs2  = (const float*)d_in[14];
    const float* gs   = (const float*)d_in[15];
    const float* bes  = (const float*)d_in[16];
    const float* rms  = (const float*)d_in[17];
    const float* rvs  = (const float*)d_in[18];
    const float* Wf   = (const float*)d_in[19];
    const float* bf   = (const float*)d_in[20];
    const float* Wo   = (const float*)d_in[21];
    const float* bo   = (const float*)d_in[22];
    float* out = (float*)d_out;

    const int* srcp = ei;
    const int* dstp = ei + EE;

    float *agg, *bufA, *bufB;
    __nv_bfloat16 *wh, *wl;
    cudaGetSymbolAddress((void**)&agg,  g_agg);
    cudaGetSymbolAddress((void**)&bufA, g_bufA);
    cudaGetSymbolAddress((void**)&bufB, g_bufB);
    cudaGetSymbolAddress((void**)&wh,   g_wh);
    cudaGetSymbolAddress((void**)&wl,   g_wl);

    cudaFuncSetAttribute(mma_gemm<128, 0>, cudaFuncAttributeMaxDynamicSharedMemorySize, SMEM_BYTES2);
    cudaFuncSetAttribute(mma_gemm<256, 0>, cudaFuncAttributeMaxDynamicSharedMemorySize, SMEM_BYTES2);
    cudaFuncSetAttribute(mma_gemm<256, 1>, cudaFuncAttributeMaxDynamicSharedMemorySize, SMEM_BYTES2);

    const int gemmGrid = (NN + 127) / 128;   // 782 blocks, BN=256 full width
    const int NB = (NN + 1023) / 1024;
    const int aggBlocks = (NN * 32 + 255) / 256;

    // ---- weights: bf16 hi/lo pre-split ----
    wconv_kernel<<<(FF * HH + 255) / 256, 256>>>(W1a, wh + 0 * 65536, wl + 0 * 65536, FF * HH);
    wconv_kernel<<<(HH * HH + 255) / 256, 256>>>(W2a, wh + 1 * 65536, wl + 1 * 65536, HH * HH);
    for (int i = 0; i < LREST; i++) {
        wconv_kernel<<<(HH * HH + 255) / 256, 256>>>(Ws1 + (size_t)i * HH * HH,
                                                     wh + (size_t)(2 + i) * 65536,
                                                     wl + (size_t)(2 + i) * 65536, HH * HH);
        wconv_kernel<<<(HH * HH + 255) / 256, 256>>>(Ws2 + (size_t)i * HH * HH,
                                                     wh + (size_t)(5 + i) * 65536,
                                                     wl + (size_t)(5 + i) * 65536, HH * HH);
    }

    // ---- CSR build (once; reused by all 4 aggregations) ----
    zero_cnt_kernel<<<(NN + 255) / 256, 256>>>();
    hist_kernel<<<(EE + 255) / 256, 256>>>(dstp);
    scan1_kernel<<<NB, 1024>>>();
    scan2_kernel<<<1, 32>>>(NB);
    scan3_kernel<<<NB, 1024>>>();
    place_kernel<<<(EE + 255) / 256, 256>>>(srcp, dstp);

    // ---- Layer 1 (input width F=128) ----
    agg_kernel<FF><<<aggBlocks, 256>>>(x, agg);
    mma_gemm<128, 0><<<gemmGrid, 256, SMEM_BYTES2>>>(agg, wh + 0 * 65536, wl + 0 * 65536,
                                                     bufA, NN, b1a, nullptr, nullptr, nullptr, nullptr);
    mma_gemm<256, 1><<<gemmGrid, 256, SMEM_BYTES2>>>(bufA, wh + 1 * 65536, wl + 1 * 65536,
                                                     bufB, NN, b2a, g_a, be_a, rm_a, rv_a);

    // ---- Layers 2..4 (width H=256) ----
    for (int i = 0; i < LREST; i++) {
        agg_kernel<HH><<<aggBlocks, 256>>>(bufB, agg);
        mma_gemm<256, 0><<<gemmGrid, 256, SMEM_BYTES2>>>(agg, wh + (size_t)(2 + i) * 65536,
                                                         wl + (size_t)(2 + i) * 65536,
                                                         bufA, NN, bs1 + i * HH,
                                                         nullptr, nullptr, nullptr, nullptr);
        mma_gemm<256, 1><<<gemmGrid, 256, SMEM_BYTES2>>>(bufA, wh + (size_t)(5 + i) * 65536,
                                                         wl + (size_t)(5 + i) * 65536,
                                                         bufB, NN, bs2 + i * HH,
                                                         gs + i * HH, bes + i * HH,
                                                         rms + i * HH, rvs + i * HH);
    }

    // ---- Pool + head ----
    zero_pool_kernel<<<(GG * HH + 255) / 256, 256>>>();
    pool_kernel<<<(NN * 32 + 255) / 256, 256>>>(bufB, batch);
    head_kernel<<<GG, 256>>>(Wf, bf, Wo, bo, out);
}

// round 12
// speedup vs baseline: 1.0584x; 1.0584x over previous
#include <cuda_runtime.h>
#include <cuda_bf16.h>
#include <math.h>
#include <stdint.h>

#define NN 100000
#define EE 1600000
#define FF 128
#define HH 256
#define GG 512
#define CC 10
#define LREST 3
#define BN_EPS 1e-5f

// ---------------- scratch (static device arrays; no allocation) --------------
__device__ float g_agg [(size_t)NN * HH];
__device__ float g_bufA[(size_t)NN * HH];
__device__ float g_bufB[(size_t)NN * HH];
__device__ float g_pooled[GG * HH];
__device__ float g_counts[GG];
__device__ __nv_bfloat16 g_wh[8 * 65536];   // weight hi parts, [K][N] natural layout
__device__ __nv_bfloat16 g_wl[8 * 65536];   // weight lo parts
// CSR build
__device__ int g_cnt[NN];
__device__ int g_off[NN];
__device__ int g_cursor[NN];
__device__ int g_ssrc[EE];
__device__ int g_bsum[128];
__device__ int g_boff[128];

// ---------------- helpers ----------------------------------------------------
__device__ __forceinline__ uint32_t smem_u32(const void* p) {
    uint32_t r;
    asm("{ .reg .u64 t; cvta.to.shared.u64 t, %1; cvt.u32.u64 %0, t; }" : "=r"(r) : "l"(p));
    return r;
}
__device__ __forceinline__ void bsplit2(float e, float o, uint32_t& hi, uint32_t& lo) {
    __nv_bfloat16 he = __float2bfloat16_rn(e);
    __nv_bfloat16 ho = __float2bfloat16_rn(o);
    float re = e - __bfloat162float(he);
    float ro = o - __bfloat162float(ho);
    __nv_bfloat16 le  = __float2bfloat16_rn(re);
    __nv_bfloat16 lo_ = __float2bfloat16_rn(ro);
    hi = ((uint32_t)__bfloat16_as_ushort(ho) << 16) | (uint32_t)__bfloat16_as_ushort(he);
    lo = ((uint32_t)__bfloat16_as_ushort(lo_) << 16) | (uint32_t)__bfloat16_as_ushort(le);
}
__device__ __forceinline__ void mma16816(float* d, const uint32_t* a, uint32_t b0, uint32_t b1) {
    asm volatile("mma.sync.aligned.m16n8k16.row.col.f32.bf16.bf16.f32 "
                 "{%0,%1,%2,%3}, {%4,%5,%6,%7}, {%8,%9}, {%0,%1,%2,%3};"
                 : "+f"(d[0]), "+f"(d[1]), "+f"(d[2]), "+f"(d[3])
                 : "r"(a[0]), "r"(a[1]), "r"(a[2]), "r"(a[3]), "r"(b0), "r"(b1));
}
__device__ __forceinline__ void ldsm4(uint32_t* r, uint32_t addr) {
    asm volatile("ldmatrix.sync.aligned.m8n8.x4.shared.b16 {%0,%1,%2,%3}, [%4];"
                 : "=r"(r[0]), "=r"(r[1]), "=r"(r[2]), "=r"(r[3]) : "r"(addr));
}
__device__ __forceinline__ void ldsm4t(uint32_t* r, uint32_t addr) {
    asm volatile("ldmatrix.sync.aligned.m8n8.x4.trans.shared.b16 {%0,%1,%2,%3}, [%4];"
                 : "=r"(r[0]), "=r"(r[1]), "=r"(r[2]), "=r"(r[3]) : "r"(addr));
}
__device__ __forceinline__ void cpasync16(uint32_t s, const void* g) {
    asm volatile("cp.async.ca.shared.global [%0], [%1], 16;"
                 :: "r"(s), "l"(g) : "memory");
}

// ---------------- CSR build ---------------------------------------------------
__global__ void zero_cnt_kernel() {
    int i = blockIdx.x * blockDim.x + threadIdx.x;
    if (i < NN) g_cnt[i] = 0;
}
__global__ void hist_kernel(const int* __restrict__ dst) {
    int e = blockIdx.x * blockDim.x + threadIdx.x;
    if (e < EE) atomicAdd(&g_cnt[dst[e]], 1);
}
__global__ __launch_bounds__(1024)
void scan1_kernel() {
    __shared__ int sh[1024];
    int i = blockIdx.x * 1024 + threadIdx.x;
    int v = (i < NN) ? g_cnt[i] : 0;
    sh[threadIdx.x] = v;
    __syncthreads();
    for (int o = 1; o < 1024; o <<= 1) {
        int t = (threadIdx.x >= o) ? sh[threadIdx.x - o] : 0;
        __syncthreads();
        sh[threadIdx.x] += t;
        __syncthreads();
    }
    if (i < NN) g_off[i] = sh[threadIdx.x] - v;
    if (threadIdx.x == 1023) g_bsum[blockIdx.x] = sh[1023];
}
// parallel single-block scan over block sums (was serial 1-thread loop)
__global__ __launch_bounds__(128)
void scan2_kernel(int nb) {
    __shared__ int sh[128];
    int t = threadIdx.x;
    int v = (t < nb) ? g_bsum[t] : 0;
    sh[t] = v;
    __syncthreads();
    for (int o = 1; o < 128; o <<= 1) {
        int u = (t >= o) ? sh[t - o] : 0;
        __syncthreads();
        sh[t] += u;
        __syncthreads();
    }
    if (t < nb) g_boff[t] = sh[t] - v;   // exclusive
}
__global__ __launch_bounds__(1024)
void scan3_kernel() {
    int i = blockIdx.x * 1024 + threadIdx.x;
    if (i < NN) {
        int o = g_off[i] + g_boff[blockIdx.x];
        g_off[i] = o;
        g_cursor[i] = o;
    }
}
__global__ void place_kernel(const int* __restrict__ src, const int* __restrict__ dst) {
    int e = blockIdx.x * blockDim.x + threadIdx.x;
    if (e < EE) {
        int p = atomicAdd(&g_cursor[dst[e]], 1);
        g_ssrc[p] = src[e];
    }
}

// ---------------- CSR aggregation: agg[d] = x[d] + sum_{s in N(d)} x[s] ------
// warp per node; 4-way unrolled edge loop (round-7 measured config)
template<int W>
__global__ __launch_bounds__(256)
void agg_kernel(const float* __restrict__ x, float* __restrict__ agg) {
    int gtid = blockIdx.x * blockDim.x + threadIdx.x;
    int d = gtid >> 5;
    int lane = gtid & 31;
    if (d >= NN) return;
    constexpr int V = W / 128;
    const float4* xv = (const float4*)x;
    float4 acc[V];
#pragma unroll
    for (int q = 0; q < V; q++) acc[q] = xv[(size_t)d * (W / 4) + lane + 32 * q];

    int beg = g_off[d];
    int cnt = g_cnt[d];
    int j = 0;
    for (; j + 4 <= cnt; j += 4) {
        int s0 = g_ssrc[beg + j];
        int s1 = g_ssrc[beg + j + 1];
        int s2 = g_ssrc[beg + j + 2];
        int s3 = g_ssrc[beg + j + 3];
        float4 v0[V], v1[V], v2[V], v3[V];
#pragma unroll
        for (int q = 0; q < V; q++) v0[q] = xv[(size_t)s0 * (W / 4) + lane + 32 * q];
#pragma unroll
        for (int q = 0; q < V; q++) v1[q] = xv[(size_t)s1 * (W / 4) + lane + 32 * q];
#pragma unroll
        for (int q = 0; q < V; q++) v2[q] = xv[(size_t)s2 * (W / 4) + lane + 32 * q];
#pragma unroll
        for (int q = 0; q < V; q++) v3[q] = xv[(size_t)s3 * (W / 4) + lane + 32 * q];
#pragma unroll
        for (int q = 0; q < V; q++) {
            acc[q].x += (v0[q].x + v1[q].x) + (v2[q].x + v3[q].x);
            acc[q].y += (v0[q].y + v1[q].y) + (v2[q].y + v3[q].y);
            acc[q].z += (v0[q].z + v1[q].z) + (v2[q].z + v3[q].z);
            acc[q].w += (v0[q].w + v1[q].w) + (v2[q].w + v3[q].w);
        }
    }
    for (; j + 2 <= cnt; j += 2) {
        int s0 = g_ssrc[beg + j];
        int s1 = g_ssrc[beg + j + 1];
        float4 v0[V], v1[V];
#pragma unroll
        for (int q = 0; q < V; q++) v0[q] = xv[(size_t)s0 * (W / 4) + lane + 32 * q];
#pragma unroll
        for (int q = 0; q < V; q++) v1[q] = xv[(size_t)s1 * (W / 4) + lane + 32 * q];
#pragma unroll
        for (int q = 0; q < V; q++) {
            acc[q].x += v0[q].x + v1[q].x;
            acc[q].y += v0[q].y + v1[q].y;
            acc[q].z += v0[q].z + v1[q].z;
            acc[q].w += v0[q].w + v1[q].w;
        }
    }
    if (j < cnt) {
        int s0 = g_ssrc[beg + j];
#pragma unroll
        for (int q = 0; q < V; q++) {
            float4 v = xv[(size_t)s0 * (W / 4) + lane + 32 * q];
            acc[q].x += v.x; acc[q].y += v.y; acc[q].z += v.z; acc[q].w += v.w;
        }
    }
    float4* av = (float4*)agg;
#pragma unroll
    for (int q = 0; q < V; q++) av[(size_t)d * (W / 4) + lane + 32 * q] = acc[q];
}

// ---------------- SMEM geometry (GEMM) — round-7 config ----------------------
static constexpr int AST  = 40;
static constexpr int BST  = 136;
static constexpr int A_SZ = 128 * AST;
static constexpr int B_SZ = 32 * BST;
static constexpr int SMEM_BYTES2 = (4 * A_SZ + 4 * B_SZ) * 2;  // 75776 B

// ---------------- bf16x3 mma GEMM: round-7 champion (m32n64, 2 CTA/SM) -------
template<int KDIM, int EPI>
__global__ __launch_bounds__(256, 2)
void mma_gemm(const float* __restrict__ A,
              const __nv_bfloat16* __restrict__ Wh,
              const __nv_bfloat16* __restrict__ Wl,
              float* __restrict__ C, int M,
              const float* __restrict__ bias,
              const float* __restrict__ gp, const float* __restrict__ bep,
              const float* __restrict__ rmp, const float* __restrict__ rvp) {
    extern __shared__ __nv_bfloat16 sm[];
    __nv_bfloat16* sAh = sm;
    __nv_bfloat16* sAl = sAh + 2 * A_SZ;
    const uint32_t sAh_u = smem_u32(sAh);
    const uint32_t sAl_u = sAh_u + 2 * A_SZ * 2;
    const uint32_t sBh_u = sAl_u + 2 * A_SZ * 2;
    const uint32_t sBl_u = sBh_u + 2 * B_SZ * 2;

    const int tid  = threadIdx.x;
    const int lane = tid & 31;
    const int wid  = tid >> 5;
    const int wm   = wid >> 1;
    const int wn   = wid & 1;
    const int rowBase = blockIdx.y * 128;
    const int colBase = blockIdx.x * 128;
    constexpr int NIT = KDIM / 32;

    float acc[2][8][4];
#pragma unroll
    for (int mi = 0; mi < 2; mi++)
#pragma unroll
        for (int ni = 0; ni < 8; ni++)
#pragma unroll
            for (int q = 0; q < 4; q++) acc[mi][ni][q] = 0.f;

    float4 ar[4];

    auto loadA = [&](int it) {
        int k0 = it * 32;
#pragma unroll
        for (int j = 0; j < 4; j++) {
            int i = tid + j * 256;
            int row = i >> 3, c4 = (i & 7) * 4;
            int gm = rowBase + row;
            ar[j] = (gm < M) ? *(const float4*)(A + (size_t)gm * KDIM + k0 + c4)
                             : make_float4(0.f, 0.f, 0.f, 0.f);
        }
    };
    auto storeA = [&](int buf) {
#pragma unroll
        for (int j = 0; j < 4; j++) {
            int i = tid + j * 256;
            int row = i >> 3, c4 = (i & 7) * 4;
            uint32_t h0, l0, h1, l1;
            bsplit2(ar[j].x, ar[j].y, h0, l0);
            bsplit2(ar[j].z, ar[j].w, h1, l1);
            uint32_t off = buf * A_SZ + row * AST + c4;
            *(uint2*)(sAh + off) = make_uint2(h0, h1);
            *(uint2*)(sAl + off) = make_uint2(l0, l1);
        }
    };
    auto cpB = [&](int it, int buf) {
        int k0 = it * 32;
#pragma unroll
        for (int t = 0; t < 2; t++) {
            int c = tid + t * 256;
            int kr = c >> 4, ci = c & 15;
            size_t goff = (size_t)(k0 + kr) * HH + colBase + ci * 8;
            uint32_t soff = (uint32_t)(buf * B_SZ + kr * BST + ci * 8) * 2;
            cpasync16(sBh_u + soff, Wh + goff);
            cpasync16(sBl_u + soff, Wl + goff);
        }
        asm volatile("cp.async.commit_group;" ::: "memory");
    };
    auto compute = [&](int buf) {
        uint32_t aB  = sAh_u + buf * A_SZ * 2;
        uint32_t alB = sAl_u + buf * A_SZ * 2;
        uint32_t bB  = sBh_u + buf * B_SZ * 2;
        uint32_t blB = sBl_u + buf * B_SZ * 2;
#pragma unroll
        for (int kk = 0; kk < 2; kk++) {
            uint32_t ahf[2][4], alf[2][4];
#pragma unroll
            for (int mi = 0; mi < 2; mi++) {
                int row = wm * 32 + mi * 16 + (lane & 15);
                int col = kk * 16 + (lane >> 4) * 8;
                uint32_t o = (uint32_t)(row * AST + col) * 2;
                ldsm4(ahf[mi], aB + o);
                ldsm4(alf[mi], alB + o);
            }
#pragma unroll
            for (int p = 0; p < 4; p++) {
                int kr = kk * 16 + (lane & 15);
                int nc = wn * 64 + p * 16 + (lane >> 4) * 8;
                uint32_t o = (uint32_t)(kr * BST + nc) * 2;
                uint32_t bh[4], bl[4];
                ldsm4t(bh, bB + o);
                ldsm4t(bl, blB + o);
#pragma unroll
                for (int mi = 0; mi < 2; mi++) {
#pragma unroll
                    for (int h = 0; h < 2; h++) {
                        float* d = acc[mi][p * 2 + h];
                        mma16816(d, ahf[mi], bh[2 * h], bh[2 * h + 1]);
                        mma16816(d, ahf[mi], bl[2 * h], bl[2 * h + 1]);
                        mma16816(d, alf[mi], bh[2 * h], bh[2 * h + 1]);
                    }
                }
            }
        }
    };

    cpB(0, 0);
    loadA(0);
    storeA(0);
    asm volatile("cp.async.wait_group 0;" ::: "memory");
    __syncthreads();

    int buf = 0;
    for (int it = 0; it < NIT; ++it) {
        if (it + 1 < NIT) {
            cpB(it + 1, buf ^ 1);
            loadA(it + 1);
        }
        compute(buf);
        if (it + 1 < NIT) {
            storeA(buf ^ 1);
            asm volatile("cp.async.wait_group 0;" ::: "memory");
            __syncthreads();
            buf ^= 1;
        }
    }

    const int g = lane >> 2, t = lane & 3;
#pragma unroll
    for (int ni = 0; ni < 8; ni++) {
        int col = colBase + wn * 64 + ni * 8 + t * 2;
        float b0 = __ldg(bias + col), b1 = __ldg(bias + col + 1);
        float sc0 = 1.f, sh0 = 0.f, sc1 = 1.f, sh1 = 0.f;
        if (EPI == 1) {
            float s0 = __ldg(gp + col)     * rsqrtf(__ldg(rvp + col)     + BN_EPS);
            float s1 = __ldg(gp + col + 1) * rsqrtf(__ldg(rvp + col + 1) + BN_EPS);
            sc0 = s0; sh0 = __ldg(bep + col)     - __ldg(rmp + col)     * s0;
            sc1 = s1; sh1 = __ldg(bep + col + 1) - __ldg(rmp + col + 1) * s1;
        }
#pragma unroll
        for (int mi = 0; mi < 2; mi++) {
            int r0 = rowBase + wm * 32 + mi * 16 + g;
#pragma unroll
            for (int half = 0; half < 2; half++) {
                int r = r0 + half * 8;
                if (r < M) {
                    float v0 = fmaxf(acc[mi][ni][half * 2]     + b0, 0.f);
                    float v1 = fmaxf(acc[mi][ni][half * 2 + 1] + b1, 0.f);
                    if (EPI == 1) { v0 = v0 * sc0 + sh0; v1 = v1 * sc1 + sh1; }
                    *(float2*)(C + (size_t)r * HH + col) = make_float2(v0, v1);
                }
            }
        }
    }
}

// ---------------- merged weight hi/lo pre-split (all 8 slots, 1 launch) ------
__global__ void wconv_all_kernel(const float* __restrict__ W1a, const float* __restrict__ W2a,
                                 const float* __restrict__ Ws1, const float* __restrict__ Ws2,
                                 __nv_bfloat16* __restrict__ Wh, __nv_bfloat16* __restrict__ Wl) {
    int i = blockIdx.x * blockDim.x + threadIdx.x;   // 0 .. 8*65536-1
    int slot = i >> 16;
    int off  = i & 65535;
    const float* src;
    if (slot == 0) {
        if (off >= FF * HH) return;                  // slot 0 holds only 128x256
        src = W1a;
    } else if (slot == 1) {
        src = W2a;
    } else if (slot < 5) {
        src = Ws1 + (size_t)(slot - 2) * 65536;
    } else {
        src = Ws2 + (size_t)(slot - 5) * 65536;
    }
    float f = src[off];
    __nv_bfloat16 h = __float2bfloat16_rn(f);
    Wh[i] = h;
    Wl[i] = __float2bfloat16_rn(f - __bfloat162float(h));
}

// ---------------- pooling ----------------------------------------------------
__global__ void zero_pool_kernel() {
    int i = blockIdx.x * blockDim.x + threadIdx.x;
    if (i < GG * HH) g_pooled[i] = 0.f;
    if (i < GG) g_counts[i] = 0.f;
}
__global__ void pool_kernel(const float* __restrict__ h, const int* __restrict__ batch) {
    int gtid = blockIdx.x * blockDim.x + threadIdx.x;
    int nd = gtid >> 5;
    int lane = gtid & 31;
    if (nd >= NN) return;
    int b = batch[nd];
    const float4* hr = (const float4*)(h + (size_t)nd * HH);
    float4* pr = (float4*)(g_pooled + b * HH);
#pragma unroll
    for (int i = 0; i < 2; ++i) {
        float4 v = hr[lane + 32 * i];
        asm volatile("red.global.add.v4.f32 [%0], {%1,%2,%3,%4};"
                     :: "l"(pr + lane + 32 * i),
                        "f"(v.x), "f"(v.y), "f"(v.z), "f"(v.w)
                     : "memory");
    }
    if (lane == 0) atomicAdd(&g_counts[b], 1.f);
}

// ---------------- head -------------------------------------------------------
__global__ __launch_bounds__(256)
void head_kernel(const float* __restrict__ Wf, const float* __restrict__ bf,
                 const float* __restrict__ Wo, const float* __restrict__ bo,
                 float* __restrict__ out) {
    __shared__ float ps[HH];
    __shared__ float hs[HH];
    __shared__ float ls[CC];
    int gph = blockIdx.x;
    int j = threadIdx.x;

    float cnt = fmaxf(g_counts[gph], 1.f);
    ps[j] = g_pooled[gph * HH + j] / cnt;
    __syncthreads();

    float acc = bf[j];
#pragma unroll 8
    for (int k = 0; k < HH; k++) acc = fmaf(ps[k], Wf[k * HH + j], acc);
    hs[j] = fmaxf(acc, 0.f);
    __syncthreads();

    if (j < CC) {
        float a = bo[j];
#pragma unroll 8
        for (int k = 0; k < HH; k++) a = fmaf(hs[k], Wo[k * CC + j], a);
        ls[j] = a;
    }
    __syncthreads();

    if (j == 0) {
        float m = -1e30f;
#pragma unroll
        for (int c = 0; c < CC; c++) m = fmaxf(m, ls[c]);
        float s = 0.f;
#pragma unroll
        for (int c = 0; c < CC; c++) s += expf(ls[c] - m);
        float lse = m + logf(s);
#pragma unroll
        for (int c = 0; c < CC; c++) out[gph * CC + c] = ls[c] - lse;
    }
}

// ---------------------------------------------------------------------------
extern "C" void kernel_launch(void* const* d_in, const int* in_sizes, int n_in,
                              void* d_out, int out_size) {
    const float* x    = (const float*)d_in[0];
    const int*   ei   = (const int*)  d_in[1];
    const int*   batch= (const int*)  d_in[2];
    const float* W1a  = (const float*)d_in[3];
    const float* b1a  = (const float*)d_in[4];
    const float* W2a  = (const float*)d_in[5];
    const float* b2a  = (const float*)d_in[6];
    const float* g_a  = (const float*)d_in[7];
    const float* be_a = (const float*)d_in[8];
    const float* rm_a = (const float*)d_in[9];
    const float* rv_a = (const float*)d_in[10];
    const float* Ws1  = (const float*)d_in[11];
    const float* bs1  = (const float*)d_in[12];
    const float* Ws2  = (const float*)d_in[13];
    const float* bs2  = (const float*)d_in[14];
    const float* gs   = (const float*)d_in[15];
    const float* bes  = (const float*)d_in[16];
    const float* rms  = (const float*)d_in[17];
    const float* rvs  = (const float*)d_in[18];
    const float* Wf   = (const float*)d_in[19];
    const float* bf   = (const float*)d_in[20];
    const float* Wo   = (const float*)d_in[21];
    const float* bo   = (const float*)d_in[22];
    float* out = (float*)d_out;

    const int* srcp = ei;
    const int* dstp = ei + EE;

    float *agg, *bufA, *bufB;
    __nv_bfloat16 *wh, *wl;
    cudaGetSymbolAddress((void**)&agg,  g_agg);
    cudaGetSymbolAddress((void**)&bufA, g_bufA);
    cudaGetSymbolAddress((void**)&bufB, g_bufB);
    cudaGetSymbolAddress((void**)&wh,   g_wh);
    cudaGetSymbolAddress((void**)&wl,   g_wl);

    cudaFuncSetAttribute(mma_gemm<128, 0>, cudaFuncAttributeMaxDynamicSharedMemorySize, SMEM_BYTES2);
    cudaFuncSetAttribute(mma_gemm<256, 0>, cudaFuncAttributeMaxDynamicSharedMemorySize, SMEM_BYTES2);
    cudaFuncSetAttribute(mma_gemm<256, 1>, cudaFuncAttributeMaxDynamicSharedMemorySize, SMEM_BYTES2);

    dim3 gemmGrid(2, (NN + 127) / 128);
    const int NB = (NN + 1023) / 1024;
    const int aggBlocks = (NN * 32 + 255) / 256;

    // ---- weights: single-launch bf16 hi/lo pre-split ----
    wconv_all_kernel<<<(8 * 65536) / 256, 256>>>(W1a, W2a, Ws1, Ws2, wh, wl);

    // ---- CSR build (once; reused by all 4 aggregations) ----
    zero_cnt_kernel<<<(NN + 255) / 256, 256>>>();
    hist_kernel<<<(EE + 255) / 256, 256>>>(dstp);
    scan1_kernel<<<NB, 1024>>>();
    scan2_kernel<<<1, 128>>>(NB);
    scan3_kernel<<<NB, 1024>>>();
    place_kernel<<<(EE + 255) / 256, 256>>>(srcp, dstp);

    // ---- Layer 1 (input width F=128) ----
    agg_kernel<FF><<<aggBlocks, 256>>>(x, agg);
    mma_gemm<128, 0><<<gemmGrid, 256, SMEM_BYTES2>>>(agg, wh + 0 * 65536, wl + 0 * 65536,
                                                     bufA, NN, b1a, nullptr, nullptr, nullptr, nullptr);
    mma_gemm<256, 1><<<gemmGrid, 256, SMEM_BYTES2>>>(bufA, wh + 1 * 65536, wl + 1 * 65536,
                                                     bufB, NN, b2a, g_a, be_a, rm_a, rv_a);

    // ---- Layers 2..4 (width H=256) ----
    for (int i = 0; i < LREST; i++) {
        agg_kernel<HH><<<aggBlocks, 256>>>(bufB, agg);
        mma_gemm<256, 0><<<gemmGrid, 256, SMEM_BYTES2>>>(agg, wh + (size_t)(2 + i) * 65536,
                                                         wl + (size_t)(2 + i) * 65536,
                                                         bufA, NN, bs1 + i * HH,
                                                         nullptr, nullptr, nullptr, nullptr);
        mma_gemm<256, 1><<<gemmGrid, 256, SMEM_BYTES2>>>(bufA, wh + (size_t)(5 + i) * 65536,
                                                         wl + (size_t)(5 + i) * 65536,
                                                         bufB, NN, bs2 + i * HH,
                                                         gs + i * HH, bes + i * HH,
                                                         rms + i * HH, rvs + i * HH);
    }

    // ---- Pool + head ----
    zero_pool_kernel<<<(GG * HH + 255) / 256, 256>>>();
    pool_kernel<<<(NN * 32 + 255) / 256, 256>>>(bufB, batch);
    head_kernel<<<GG, 256>>>(Wf, bf, Wo, bo, out);
}